// round 2
// baseline (speedup 1.0000x reference)
#include <cuda_runtime.h>
#include <cmath>

#define BB 8
#define CC 256
#define HH 80
#define WW 80
#define HW (HH*WW)           // 6400
#define NPIX (BB*HW)         // 51200
#define PI_F 3.14159265358979323846f

// -------------------- scratch (static device globals; no cudaMalloc) -----
__device__ float g_h2[(size_t)BB*CC*HW];       // 52.4 MB
__device__ float g_buf1[(size_t)BB*2*CC*HW];   // 104.8 MB (up to 512 ch)
__device__ float g_buf2[(size_t)BB*2*CC*HW];   // 104.8 MB

__device__ __forceinline__ float gelu_exact(float v) {
    return 0.5f * v * (1.0f + erff(v * 0.70710678118654752f));
}

// ==========================================================================
// Kernel 1: fused BatchNorm + SpectralGating (closed-form Hilbert along W)
//   h2 = (a*s)*x + (b*s)*(x circ-conv t) + a*(beta - mean*s)
//   t[n] = -(2/W) cot(pi n / W) for odd n, else 0.
// block = 4 rows x 80 threads
// ==========================================================================
__global__ __launch_bounds__(320)
void spectral_kernel(const float* __restrict__ x,
                     const float* __restrict__ gamma,
                     const float* __restrict__ beta,
                     const float* __restrict__ mean,
                     const float* __restrict__ var,
                     const float* __restrict__ ar,
                     const float* __restrict__ ai,
                     float* __restrict__ out)
{
    __shared__ float taps[WW];
    __shared__ float xs[4][WW];

    const int tt = threadIdx.x;
    const int tn = tt % WW;
    const int tr = tt / WW;

    if (tt < WW) {
        float t = 0.0f;
        if (tt & 1) {
            float ang = PI_F * (float)tt / (float)WW;
            t = -(2.0f / (float)WW) * (cosf(ang) / sinf(ang));
        }
        taps[tt] = t;
    }

    const int row = blockIdx.x * 4 + tr;       // 0 .. B*C*H-1
    const int c = (row / HH) % CC;
    const size_t base = (size_t)row * WW;

    const float xv = x[base + tn];
    xs[tr][tn] = xv;
    __syncthreads();

    float u = 0.0f;
    #pragma unroll
    for (int j = 1; j < WW; j += 2) {
        int idx = tn - j;
        if (idx < 0) idx += WW;
        u += taps[j] * xs[tr][idx];
    }

    const float s   = gamma[c] * rsqrtf(var[c] + 1e-5f);
    const float tc  = beta[c] - mean[c] * s;
    const float A   = ar[c] * s;
    const float Bc  = ai[c] * s;
    const float Cc  = ar[c] * tc;

    out[base + tn] = A * xv + Bc * u + Cc;
}

// ==========================================================================
// Kernel 2: conv1x1 as GEMM.  out[b,o,p] = sum_c W[o,c]*in[b,c,p] + bias[o]
// Tiles: BM=128 (out ch), BN=128 (pixels), BK=16. 256 threads, 8x8 microtile.
// ACT: 0=none, 1=gelu.  RES: fuse residual add.
// ==========================================================================
template<int CIN, int COUT, int ACT, bool RES>
__global__ __launch_bounds__(256)
void conv1x1_kernel(const float* __restrict__ in,
                    const float* __restrict__ wgt,
                    const float* __restrict__ bias,
                    const float* __restrict__ res,
                    float* __restrict__ out)
{
    constexpr int BM = 128, BN = 128, BK = 16;
    __shared__ float As[BK][BM];
    __shared__ float Bs[BK][BN];

    const int bn = blockIdx.x * BN;          // pixel offset within batch
    const int bm = blockIdx.y * BM;          // out-channel offset
    const int bz = blockIdx.z;               // batch

    const float* inb  = in  + (size_t)bz * CIN  * HW;
    float*       outb = out + (size_t)bz * COUT * HW;
    const float* resb = RES ? (res + (size_t)bz * COUT * HW) : nullptr;

    const int tid = threadIdx.x;
    const int tx = tid % 16;                 // pixel group
    const int ty = tid / 16;                 // channel group

    float acc[8][8];
    #pragma unroll
    for (int i = 0; i < 8; i++)
        #pragma unroll
        for (int j = 0; j < 8; j++) acc[i][j] = 0.0f;

    // load mappings
    const int am = tid / 2;                  // 0..127 (row of W)
    const int akq = (tid % 2) * 8;           // 0 or 8 (k offset)
    const int bk = tid / 16;                 // 0..15 (k row of B tile)
    const int bc4 = (tid % 16) * 4;          // 0..60 (col quad)

    for (int k0 = 0; k0 < CIN; k0 += BK) {
        // As[kk][m] = wgt[(bm+m)*CIN + k0+kk]   (transpose on store)
        {
            const float4 w0 = *(const float4*)&wgt[(size_t)(bm + am) * CIN + k0 + akq];
            const float4 w1 = *(const float4*)&wgt[(size_t)(bm + am) * CIN + k0 + akq + 4];
            As[akq + 0][am] = w0.x; As[akq + 1][am] = w0.y;
            As[akq + 2][am] = w0.z; As[akq + 3][am] = w0.w;
            As[akq + 4][am] = w1.x; As[akq + 5][am] = w1.y;
            As[akq + 6][am] = w1.z; As[akq + 7][am] = w1.w;
        }
        // Bs[kk][n] = inb[(k0+kk)*HW + bn + n]
        {
            const float4 b0 = *(const float4*)&inb[(size_t)(k0 + bk) * HW + bn + bc4];
            const float4 b1 = *(const float4*)&inb[(size_t)(k0 + bk) * HW + bn + bc4 + 64];
            *(float4*)&Bs[bk][bc4]      = b0;
            *(float4*)&Bs[bk][bc4 + 64] = b1;
        }
        __syncthreads();

        #pragma unroll
        for (int kk = 0; kk < BK; kk++) {
            float a[8], b[8];
            const float4 a0 = *(const float4*)&As[kk][ty * 8];
            const float4 a1 = *(const float4*)&As[kk][ty * 8 + 4];
            const float4 b0 = *(const float4*)&Bs[kk][tx * 8];
            const float4 b1 = *(const float4*)&Bs[kk][tx * 8 + 4];
            a[0]=a0.x; a[1]=a0.y; a[2]=a0.z; a[3]=a0.w;
            a[4]=a1.x; a[5]=a1.y; a[6]=a1.z; a[7]=a1.w;
            b[0]=b0.x; b[1]=b0.y; b[2]=b0.z; b[3]=b0.w;
            b[4]=b1.x; b[5]=b1.y; b[6]=b1.z; b[7]=b1.w;
            #pragma unroll
            for (int i = 0; i < 8; i++)
                #pragma unroll
                for (int j = 0; j < 8; j++)
                    acc[i][j] = fmaf(a[i], b[j], acc[i][j]);
        }
        __syncthreads();
    }

    // epilogue
    #pragma unroll
    for (int i = 0; i < 8; i++) {
        const int m = bm + ty * 8 + i;
        const float bv = bias[m];
        float* orow = &outb[(size_t)m * HW + bn + tx * 8];
        #pragma unroll
        for (int j4 = 0; j4 < 2; j4++) {
            float4 v;
            v.x = acc[i][j4 * 4 + 0] + bv;
            v.y = acc[i][j4 * 4 + 1] + bv;
            v.z = acc[i][j4 * 4 + 2] + bv;
            v.w = acc[i][j4 * 4 + 3] + bv;
            if (ACT == 1) {
                v.x = gelu_exact(v.x); v.y = gelu_exact(v.y);
                v.z = gelu_exact(v.z); v.w = gelu_exact(v.w);
            }
            if (RES) {
                const float4 r = *(const float4*)&resb[(size_t)m * HW + bn + tx * 8 + j4 * 4];
                v.x += r.x; v.y += r.y; v.z += r.z; v.w += r.w;
            }
            *(float4*)&orow[j4 * 4] = v;
        }
    }
}

// ==========================================================================
// Kernel 3: depthwise 3x3 (SAME, zero pad) + bias + exact GELU
// ==========================================================================
__global__ __launch_bounds__(256)
void dwgelu_kernel(const float* __restrict__ in,
                   const float* __restrict__ w,
                   const float* __restrict__ b,
                   float* __restrict__ out)
{
    const int idx = blockIdx.x * 256 + threadIdx.x;   // over B*C*H*W
    const int wp = idx % WW;
    const int h  = (idx / WW) % HH;
    const int bc = idx / HW;
    const int c  = bc % CC;

    const float* p = in + (size_t)bc * HW;
    const float* wc = w + c * 9;

    float s = b[c];
    #pragma unroll
    for (int ky = 0; ky < 3; ky++) {
        const int hy = h + ky - 1;
        if (hy < 0 || hy >= HH) continue;
        #pragma unroll
        for (int kx = 0; kx < 3; kx++) {
            const int wx = wp + kx - 1;
            if (wx < 0 || wx >= WW) continue;
            s = fmaf(wc[ky * 3 + kx], p[hy * WW + wx], s);
        }
    }
    out[idx] = gelu_exact(s);
}

// ==========================================================================
// launch
// ==========================================================================
extern "C" void kernel_launch(void* const* d_in, const int* in_sizes, int n_in,
                              void* d_out, int out_size)
{
    const float* x        = (const float*)d_in[0];
    const float* bn_gamma = (const float*)d_in[1];
    const float* bn_beta  = (const float*)d_in[2];
    const float* bn_mean  = (const float*)d_in[3];
    const float* bn_var   = (const float*)d_in[4];
    const float* a_real   = (const float*)d_in[5];
    const float* a_imag   = (const float*)d_in[6];
    const float* pi_w     = (const float*)d_in[7];
    const float* pi_b     = (const float*)d_in[8];
    const float* dw_w     = (const float*)d_in[9];
    const float* dw_b     = (const float*)d_in[10];
    const float* fpw_w    = (const float*)d_in[11];
    const float* fpw_b    = (const float*)d_in[12];
    const float* ffn1_w   = (const float*)d_in[13];
    const float* ffn1_b   = (const float*)d_in[14];
    const float* ffn2_w   = (const float*)d_in[15];
    const float* ffn2_b   = (const float*)d_in[16];
    const float* po_w     = (const float*)d_in[17];
    const float* po_b     = (const float*)d_in[18];
    const float* post_w   = (const float*)d_in[19];
    const float* post_b   = (const float*)d_in[20];
    float* out = (float*)d_out;

    float* h2   = nullptr;
    float* buf1 = nullptr;
    float* buf2 = nullptr;
    cudaGetSymbolAddress((void**)&h2,   g_h2);
    cudaGetSymbolAddress((void**)&buf1, g_buf1);
    cudaGetSymbolAddress((void**)&buf2, g_buf2);

    // 1) BN + spectral gating (closed form)
    spectral_kernel<<<(BB * CC * HH) / 4, 320>>>(
        x, bn_gamma, bn_beta, bn_mean, bn_var, a_real, a_imag, h2);

    dim3 g256(HW / 128, CC / 128, BB);        // (50, 2, 8)
    dim3 g512(HW / 128, (2 * CC) / 128, BB);  // (50, 4, 8)

    // 2) proj_in
    conv1x1_kernel<256, 256, 0, false><<<g256, 256>>>(h2, pi_w, pi_b, nullptr, buf1);
    // 3) dw3x3 + gelu
    dwgelu_kernel<<<(BB * CC * HW) / 256, 256>>>(buf1, dw_w, dw_b, buf2);
    // 4) fpw
    conv1x1_kernel<256, 256, 0, false><<<g256, 256>>>(buf2, fpw_w, fpw_b, nullptr, buf1);
    // 5) ffn1 + gelu (256 -> 512)
    conv1x1_kernel<256, 512, 1, false><<<g512, 256>>>(buf1, ffn1_w, ffn1_b, nullptr, buf2);
    // 6) ffn2 (512 -> 256)
    conv1x1_kernel<512, 256, 0, false><<<g256, 256>>>(buf2, ffn2_w, ffn2_b, nullptr, buf1);
    // 7) proj_out + res2 (h2)
    conv1x1_kernel<256, 256, 0, true><<<g256, 256>>>(buf1, po_w, po_b, h2, buf2);
    // 8) post conv + outer residual (x)
    conv1x1_kernel<256, 256, 0, true><<<g256, 256>>>(buf2, post_w, post_b, x, out);
}

// round 3
// speedup vs baseline: 3.0522x; 3.0522x over previous
#include <cuda_runtime.h>
#include <cuda_bf16.h>
#include <cmath>
#include <cstdint>

#define BB 8
#define CC 256
#define HH 80
#define WW 80
#define HW (HH*WW)           // 6400
#define PI_F 3.14159265358979323846f

// GEMM tiling
#define BM 128
#define BN 128
#define BK 32
#define AST 40               // padded A smem stride (bf16 elems)
#define BSTR 136             // padded B smem stride (bf16 elems)
#define ASZ (BM*AST)         // 5120
#define BSZ (BK*BSTR)        // 4352

// weight segment offsets in bf16 scratch
#define W_PI    0
#define W_FPW   65536
#define W_FFN1  131072
#define W_FFN2  262144
#define W_PO    393216
#define W_POST  458752
#define W_TOTAL 524288

// -------------------- scratch (static device globals) --------------------
__device__ float          g_h2f[(size_t)BB*CC*HW];          // fp32 residual h2
__device__ __nv_bfloat16  g_h2b[(size_t)BB*CC*HW];          // bf16 h2 (GEMM input)
__device__ __nv_bfloat16  g_b1[(size_t)BB*2*CC*HW];         // bf16 activations (<=512ch)
__device__ __nv_bfloat16  g_b2[(size_t)BB*2*CC*HW];
__device__ __nv_bfloat16  g_wbf[W_TOTAL];                   // bf16 weights

__device__ __forceinline__ float gelu_exact(float v) {
    return 0.5f * v * (1.0f + erff(v * 0.70710678118654752f));
}

// -------------------- PTX helpers ----------------------------------------
__device__ __forceinline__ void ldsm4(uint32_t* r, uint32_t addr) {
    asm volatile("ldmatrix.sync.aligned.m8n8.x4.shared.b16 {%0,%1,%2,%3}, [%4];\n"
        : "=r"(r[0]), "=r"(r[1]), "=r"(r[2]), "=r"(r[3]) : "r"(addr));
}
__device__ __forceinline__ void ldsm4t(uint32_t* r, uint32_t addr) {
    asm volatile("ldmatrix.sync.aligned.m8n8.x4.trans.shared.b16 {%0,%1,%2,%3}, [%4];\n"
        : "=r"(r[0]), "=r"(r[1]), "=r"(r[2]), "=r"(r[3]) : "r"(addr));
}
__device__ __forceinline__ void mma16816(float* d, const uint32_t* a, const uint32_t* b) {
    asm volatile(
        "mma.sync.aligned.m16n8k16.row.col.f32.bf16.bf16.f32 "
        "{%0,%1,%2,%3}, {%4,%5,%6,%7}, {%8,%9}, {%0,%1,%2,%3};\n"
        : "+f"(d[0]), "+f"(d[1]), "+f"(d[2]), "+f"(d[3])
        : "r"(a[0]), "r"(a[1]), "r"(a[2]), "r"(a[3]), "r"(b[0]), "r"(b[1]));
}
__device__ __forceinline__ void cpasync16(uint32_t smem, const void* g) {
    asm volatile("cp.async.cg.shared.global [%0], [%1], 16;\n" :: "r"(smem), "l"(g));
}

// ==========================================================================
// Kernel 1: fused BatchNorm + SpectralGating (closed-form Hilbert along W)
// ==========================================================================
__global__ __launch_bounds__(320)
void spectral_kernel(const float* __restrict__ x,
                     const float* __restrict__ gamma,
                     const float* __restrict__ beta,
                     const float* __restrict__ mean,
                     const float* __restrict__ var,
                     const float* __restrict__ ar,
                     const float* __restrict__ ai,
                     float* __restrict__ outf,
                     __nv_bfloat16* __restrict__ outb)
{
    __shared__ float taps[WW];
    __shared__ float xs[4][WW];

    const int tt = threadIdx.x;
    const int tn = tt % WW;
    const int tr = tt / WW;

    if (tt < WW) {
        float t = 0.0f;
        if (tt & 1) {
            float ang = PI_F * (float)tt / (float)WW;
            t = -(2.0f / (float)WW) * (cosf(ang) / sinf(ang));
        }
        taps[tt] = t;
    }

    const int row = blockIdx.x * 4 + tr;
    const int c = (row / HH) % CC;
    const size_t base = (size_t)row * WW;

    const float xv = x[base + tn];
    xs[tr][tn] = xv;
    __syncthreads();

    float u = 0.0f;
    #pragma unroll
    for (int j = 1; j < WW; j += 2) {
        int idx = tn - j;
        if (idx < 0) idx += WW;
        u += taps[j] * xs[tr][idx];
    }

    const float s   = gamma[c] * rsqrtf(var[c] + 1e-5f);
    const float tc  = beta[c] - mean[c] * s;
    const float A   = ar[c] * s;
    const float Bc  = ai[c] * s;
    const float Cc  = ar[c] * tc;

    const float r = A * xv + Bc * u + Cc;
    outf[base + tn] = r;
    outb[base + tn] = __float2bfloat16(r);
}

// ==========================================================================
// Weight fp32 -> bf16 conversion (all 6 conv1x1 weights)
// ==========================================================================
__global__ __launch_bounds__(256)
void wconv_kernel(const float* __restrict__ pi, const float* __restrict__ fpw,
                  const float* __restrict__ f1, const float* __restrict__ f2,
                  const float* __restrict__ po, const float* __restrict__ post,
                  __nv_bfloat16* __restrict__ o)
{
    const int i = blockIdx.x * 256 + threadIdx.x;
    float v;
    if      (i < W_FPW)  v = pi[i];
    else if (i < W_FFN1) v = fpw[i - W_FPW];
    else if (i < W_FFN2) v = f1[i - W_FFN1];
    else if (i < W_PO)   v = f2[i - W_FFN2];
    else if (i < W_POST) v = po[i - W_PO];
    else                 v = post[i - W_POST];
    o[i] = __float2bfloat16(v);
}

// ==========================================================================
// Kernel 2: tensor-core conv1x1 GEMM.
//   out[b,o,p] = act( sum_c W[o,c]*in[b,c,p] + bias[o] ) (+ res[b,o,p])
// bf16 in/weights, fp32 accum. 256 thr = 8 warps (2x4), warp tile 64x32.
// ==========================================================================
template<int CIN, int ACT, int RES, int OUTF32>
__global__ __launch_bounds__(256)
void gemm_tc(const __nv_bfloat16* __restrict__ in,
             const __nv_bfloat16* __restrict__ wgt,
             const float* __restrict__ bias,
             const float* __restrict__ res,
             void* __restrict__ outp)
{
    __shared__ __nv_bfloat16 As[2 * ASZ];
    __shared__ __nv_bfloat16 Bs[2 * BSZ];

    const int tid = threadIdx.x;
    const int bn = blockIdx.x * BN;
    const int bm = blockIdx.y * BM;
    const int bz = blockIdx.z;
    const int COUT = gridDim.y << 7;

    const __nv_bfloat16* inb = in + (size_t)bz * CIN * HW;

    const uint32_t sA = (uint32_t)__cvta_generic_to_shared(As);
    const uint32_t sB = (uint32_t)__cvta_generic_to_shared(Bs);

    // load-chunk coords (16B chunks of 8 bf16)
    const int a_r = tid >> 2, a_c = (tid & 3) << 3;
    const int b_k = tid >> 4, b_n = (tid & 15) << 3;

    // fragment coords
    const int lane = tid & 31, wid = tid >> 5;
    const int wm = (wid >> 2) * 64;
    const int wn = (wid & 3) * 32;
    const int lr = lane & 15;
    const int lc = (lane >> 4) << 3;

    float acc[4][4][4];
    #pragma unroll
    for (int i = 0; i < 4; i++)
        #pragma unroll
        for (int j = 0; j < 4; j++)
            #pragma unroll
            for (int k = 0; k < 4; k++) acc[i][j][k] = 0.0f;

    constexpr int NK = CIN / BK;

    auto load_stage = [&](int s, int k0) {
        const uint32_t aOff = sA + s * (ASZ * 2);
        const uint32_t bOff = sB + s * (BSZ * 2);
        cpasync16(aOff + (a_r * AST + a_c) * 2,
                  wgt + (size_t)(bm + a_r) * CIN + k0 + a_c);
        cpasync16(aOff + ((a_r + 64) * AST + a_c) * 2,
                  wgt + (size_t)(bm + a_r + 64) * CIN + k0 + a_c);
        cpasync16(bOff + (b_k * BSTR + b_n) * 2,
                  inb + (size_t)(k0 + b_k) * HW + bn + b_n);
        cpasync16(bOff + ((b_k + 16) * BSTR + b_n) * 2,
                  inb + (size_t)(k0 + b_k + 16) * HW + bn + b_n);
        asm volatile("cp.async.commit_group;\n");
    };

    load_stage(0, 0);

    for (int it = 0; it < NK; ++it) {
        if (it + 1 < NK) {
            load_stage((it + 1) & 1, (it + 1) * BK);
            asm volatile("cp.async.wait_group 1;\n");
        } else {
            asm volatile("cp.async.wait_group 0;\n");
        }
        __syncthreads();

        const int s = it & 1;
        const uint32_t aBase = sA + s * (ASZ * 2);
        const uint32_t bBase = sB + s * (BSZ * 2);

        #pragma unroll
        for (int kk = 0; kk < 2; kk++) {
            uint32_t a[4][4], b[2][4];
            #pragma unroll
            for (int mi = 0; mi < 4; mi++)
                ldsm4(a[mi], aBase + (((wm + mi * 16 + lr) * AST) + kk * 16 + lc) * 2);
            #pragma unroll
            for (int nt = 0; nt < 2; nt++)
                ldsm4t(b[nt], bBase + (((kk * 16 + lr) * BSTR) + wn + nt * 16 + lc) * 2);
            #pragma unroll
            for (int mi = 0; mi < 4; mi++)
                #pragma unroll
                for (int ni = 0; ni < 4; ni++)
                    mma16816(acc[mi][ni], a[mi], &b[ni >> 1][(ni & 1) * 2]);
        }
        __syncthreads();
    }

    // epilogue
    #pragma unroll
    for (int mi = 0; mi < 4; mi++) {
        const int m_base = bm + wm + mi * 16 + (lane >> 2);
        #pragma unroll
        for (int rg = 0; rg < 2; rg++) {
            const int mm = m_base + rg * 8;
            const float bv = bias[mm];
            #pragma unroll
            for (int ni = 0; ni < 4; ni++) {
                float v0 = acc[mi][ni][rg * 2 + 0] + bv;
                float v1 = acc[mi][ni][rg * 2 + 1] + bv;
                if (ACT == 1) { v0 = gelu_exact(v0); v1 = gelu_exact(v1); }
                const int n = bn + wn + ni * 8 + (lane & 3) * 2;
                const size_t off = ((size_t)bz * COUT + mm) * HW + n;
                if (RES) {
                    const float2 r = *(const float2*)(res + off);
                    v0 += r.x; v1 += r.y;
                }
                if (OUTF32) {
                    float2 o; o.x = v0; o.y = v1;
                    *(float2*)((float*)outp + off) = o;
                } else {
                    __nv_bfloat162 o;
                    o.x = __float2bfloat16(v0); o.y = __float2bfloat16(v1);
                    *(__nv_bfloat162*)((__nv_bfloat16*)outp + off) = o;
                }
            }
        }
    }
}

// ==========================================================================
// Kernel 3: depthwise 3x3 (SAME, zero pad) + bias + exact GELU (bf16 io)
// ==========================================================================
__global__ __launch_bounds__(256)
void dwgelu_kernel(const __nv_bfloat16* __restrict__ in,
                   const float* __restrict__ w,
                   const float* __restrict__ b,
                   __nv_bfloat16* __restrict__ out)
{
    const int idx = blockIdx.x * 256 + threadIdx.x;
    const int wp = idx % WW;
    const int h  = (idx / WW) % HH;
    const int bc = idx / HW;
    const int c  = bc % CC;

    const __nv_bfloat16* p = in + (size_t)bc * HW;
    const float* wc = w + c * 9;

    float s = b[c];
    #pragma unroll
    for (int ky = 0; ky < 3; ky++) {
        const int hy = h + ky - 1;
        if (hy < 0 || hy >= HH) continue;
        #pragma unroll
        for (int kx = 0; kx < 3; kx++) {
            const int wx = wp + kx - 1;
            if (wx < 0 || wx >= WW) continue;
            s = fmaf(wc[ky * 3 + kx], __bfloat162float(p[hy * WW + wx]), s);
        }
    }
    out[idx] = __float2bfloat16(gelu_exact(s));
}

// ==========================================================================
// launch
// ==========================================================================
extern "C" void kernel_launch(void* const* d_in, const int* in_sizes, int n_in,
                              void* d_out, int out_size)
{
    const float* x        = (const float*)d_in[0];
    const float* bn_gamma = (const float*)d_in[1];
    const float* bn_beta  = (const float*)d_in[2];
    const float* bn_mean  = (const float*)d_in[3];
    const float* bn_var   = (const float*)d_in[4];
    const float* a_real   = (const float*)d_in[5];
    const float* a_imag   = (const float*)d_in[6];
    const float* pi_w     = (const float*)d_in[7];
    const float* pi_b     = (const float*)d_in[8];
    const float* dw_w     = (const float*)d_in[9];
    const float* dw_b     = (const float*)d_in[10];
    const float* fpw_w    = (const float*)d_in[11];
    const float* fpw_b    = (const float*)d_in[12];
    const float* ffn1_w   = (const float*)d_in[13];
    const float* ffn1_b   = (const float*)d_in[14];
    const float* ffn2_w   = (const float*)d_in[15];
    const float* ffn2_b   = (const float*)d_in[16];
    const float* po_w     = (const float*)d_in[17];
    const float* po_b     = (const float*)d_in[18];
    const float* post_w   = (const float*)d_in[19];
    const float* post_b   = (const float*)d_in[20];
    float* out = (float*)d_out;

    float* h2f = nullptr;
    __nv_bfloat16 *h2b = nullptr, *b1 = nullptr, *b2 = nullptr, *wbf = nullptr;
    cudaGetSymbolAddress((void**)&h2f, g_h2f);
    cudaGetSymbolAddress((void**)&h2b, g_h2b);
    cudaGetSymbolAddress((void**)&b1,  g_b1);
    cudaGetSymbolAddress((void**)&b2,  g_b2);
    cudaGetSymbolAddress((void**)&wbf, g_wbf);

    // 0) weights -> bf16
    wconv_kernel<<<W_TOTAL / 256, 256>>>(pi_w, fpw_w, ffn1_w, ffn2_w, po_w, post_w, wbf);

    // 1) BN + spectral gating (closed form), fp32 + bf16 outputs
    spectral_kernel<<<(BB * CC * HH) / 4, 320>>>(
        x, bn_gamma, bn_beta, bn_mean, bn_var, a_real, a_imag, h2f, h2b);

    dim3 g256(HW / 128, CC / 128, BB);        // (50, 2, 8)
    dim3 g512(HW / 128, (2 * CC) / 128, BB);  // (50, 4, 8)

    // 2) proj_in
    gemm_tc<256, 0, 0, 0><<<g256, 256>>>(h2b, wbf + W_PI, pi_b, nullptr, b1);
    // 3) dw3x3 + gelu
    dwgelu_kernel<<<(BB * CC * HW) / 256, 256>>>(b1, dw_w, dw_b, b2);
    // 4) fpw
    gemm_tc<256, 0, 0, 0><<<g256, 256>>>(b2, wbf + W_FPW, fpw_b, nullptr, b1);
    // 5) ffn1 + gelu (256 -> 512)
    gemm_tc<256, 1, 0, 0><<<g512, 256>>>(b1, wbf + W_FFN1, ffn1_b, nullptr, b2);
    // 6) ffn2 (512 -> 256)
    gemm_tc<512, 0, 0, 0><<<g256, 256>>>(b2, wbf + W_FFN2, ffn2_b, nullptr, b1);
    // 7) proj_out + res2 (h2 fp32)
    gemm_tc<256, 0, 1, 0><<<g256, 256>>>(b1, wbf + W_PO, po_b, h2f, b2);
    // 8) post conv + outer residual (x fp32), fp32 out
    gemm_tc<256, 0, 1, 1><<<g256, 256>>>(b2, wbf + W_POST, post_b, x, out);
}

// round 4
// speedup vs baseline: 3.1712x; 1.0390x over previous
#include <cuda_runtime.h>
#include <cuda_bf16.h>
#include <cmath>
#include <cstdint>

#define BB 8
#define CC 256
#define HH 80
#define WW 80
#define HW (HH*WW)           // 6400
#define PI_F 3.14159265358979323846f

// GEMM tiling
#define BM 128
#define BN 256
#define BK 32
#define AST 40               // padded A smem stride (bf16)
#define BSTR 264             // padded B smem stride (bf16)
#define ASZ (BM*AST)         // 5120
#define BSZ (BK*BSTR)        // 8448
#define NSTAGE 3
#define GSMEM (NSTAGE*(ASZ+BSZ)*2)   // 81408 bytes

// weight segment offsets in bf16 scratch
#define W_PI    0
#define W_FPW   65536
#define W_FFN1  131072       // 512x256
#define W_COMB  262144       // 256x512 (po @ ffn2)
#define W_POST  393216
#define W_TOTAL 458752

// -------------------- scratch (static device globals) --------------------
__device__ float          g_h2f[(size_t)BB*CC*HW];
__device__ __nv_bfloat16  g_h2b[(size_t)BB*CC*HW];
__device__ __nv_bfloat16  g_b1[(size_t)BB*2*CC*HW];
__device__ __nv_bfloat16  g_b2[(size_t)BB*2*CC*HW];
__device__ __nv_bfloat16  g_wbf[W_TOTAL];
__device__ float          g_biasc[CC];

__device__ __forceinline__ float gelu_exact(float v) {
    return 0.5f * v * (1.0f + erff(v * 0.70710678118654752f));
}

// -------------------- PTX helpers ----------------------------------------
__device__ __forceinline__ void ldsm4(uint32_t* r, uint32_t addr) {
    asm volatile("ldmatrix.sync.aligned.m8n8.x4.shared.b16 {%0,%1,%2,%3}, [%4];\n"
        : "=r"(r[0]), "=r"(r[1]), "=r"(r[2]), "=r"(r[3]) : "r"(addr));
}
__device__ __forceinline__ void ldsm4t(uint32_t* r, uint32_t addr) {
    asm volatile("ldmatrix.sync.aligned.m8n8.x4.trans.shared.b16 {%0,%1,%2,%3}, [%4];\n"
        : "=r"(r[0]), "=r"(r[1]), "=r"(r[2]), "=r"(r[3]) : "r"(addr));
}
__device__ __forceinline__ void mma16816(float* d, const uint32_t* a, const uint32_t* b) {
    asm volatile(
        "mma.sync.aligned.m16n8k16.row.col.f32.bf16.bf16.f32 "
        "{%0,%1,%2,%3}, {%4,%5,%6,%7}, {%8,%9}, {%0,%1,%2,%3};\n"
        : "+f"(d[0]), "+f"(d[1]), "+f"(d[2]), "+f"(d[3])
        : "r"(a[0]), "r"(a[1]), "r"(a[2]), "r"(a[3]), "r"(b[0]), "r"(b[1]));
}
__device__ __forceinline__ void cpasync16(uint32_t smem, const void* g) {
    asm volatile("cp.async.cg.shared.global [%0], [%1], 16;\n" :: "r"(smem), "l"(g));
}

// ==========================================================================
// Kernel 1: fused BatchNorm + SpectralGating (closed-form Hilbert along W)
// ==========================================================================
__global__ __launch_bounds__(320)
void spectral_kernel(const float* __restrict__ x,
                     const float* __restrict__ gamma,
                     const float* __restrict__ beta,
                     const float* __restrict__ mean,
                     const float* __restrict__ var,
                     const float* __restrict__ ar,
                     const float* __restrict__ ai,
                     float* __restrict__ outf,
                     __nv_bfloat16* __restrict__ outb)
{
    __shared__ float taps[WW];
    __shared__ float xs[4][WW];

    const int tt = threadIdx.x;
    const int tn = tt % WW;
    const int tr = tt / WW;

    if (tt < WW) {
        float t = 0.0f;
        if (tt & 1) {
            float ang = PI_F * (float)tt / (float)WW;
            t = -(2.0f / (float)WW) * (cosf(ang) / sinf(ang));
        }
        taps[tt] = t;
    }

    const int row = blockIdx.x * 4 + tr;
    const int c = (row / HH) % CC;
    const size_t base = (size_t)row * WW;

    const float xv = x[base + tn];
    xs[tr][tn] = xv;
    __syncthreads();

    float u = 0.0f;
    #pragma unroll
    for (int j = 1; j < WW; j += 2) {
        int idx = tn - j;
        if (idx < 0) idx += WW;
        u += taps[j] * xs[tr][idx];
    }

    const float s   = gamma[c] * rsqrtf(var[c] + 1e-5f);
    const float tc  = beta[c] - mean[c] * s;
    const float A   = ar[c] * s;
    const float Bc  = ai[c] * s;
    const float Cc  = ar[c] * tc;

    const float r = A * xv + Bc * u + Cc;
    outf[base + tn] = r;
    outb[base + tn] = __float2bfloat16(r);
}

// ==========================================================================
// Weight fp32 -> bf16 conversion (pi, fpw, ffn1, post)
// ==========================================================================
__global__ __launch_bounds__(256)
void wconv_kernel(const float* __restrict__ pi, const float* __restrict__ fpw,
                  const float* __restrict__ f1, const float* __restrict__ post,
                  __nv_bfloat16* __restrict__ o)
{
    const int i = blockIdx.x * 256 + threadIdx.x;   // 0 .. 327679
    float v; int dst;
    if      (i < 65536)  { v = pi[i];            dst = W_PI   + i; }
    else if (i < 131072) { v = fpw[i - 65536];   dst = W_FPW  + (i - 65536); }
    else if (i < 262144) { v = f1[i - 131072];   dst = W_FFN1 + (i - 131072); }
    else                 { v = post[i - 262144]; dst = W_POST + (i - 262144); }
    o[dst] = __float2bfloat16(v);
}

// ==========================================================================
// W_comb = po_w @ ffn2_w   (256x256 @ 256x512 -> 256x512, fp32 accum -> bf16)
// ==========================================================================
__global__ __launch_bounds__(512)
void wprod_kernel(const float* __restrict__ po_w, const float* __restrict__ ffn2_w,
                  __nv_bfloat16* __restrict__ o)
{
    __shared__ float prow[256];
    const int oo = blockIdx.x;
    for (int i = threadIdx.x; i < 256; i += 512) prow[i] = po_w[oo * 256 + i];
    __syncthreads();
    float s = 0.0f;
    #pragma unroll 8
    for (int c = 0; c < 256; c++)
        s = fmaf(prow[c], ffn2_w[(size_t)c * 512 + threadIdx.x], s);
    o[(size_t)oo * 512 + threadIdx.x] = __float2bfloat16(s);
}

// bias_comb = po_b + po_w @ ffn2_b
__global__ void biasc_kernel(const float* __restrict__ po_w, const float* __restrict__ po_b,
                             const float* __restrict__ ffn2_b, float* __restrict__ o)
{
    const int oo = threadIdx.x;
    float s = po_b[oo];
    for (int c = 0; c < 256; c++)
        s = fmaf(po_w[oo * 256 + c], ffn2_b[c], s);
    o[oo] = s;
}

// ==========================================================================
// Kernel 2: tensor-core conv1x1 GEMM. 128x256x32 tiles, 8 warps, 64x64/warp,
// 3-stage cp.async pipeline, dynamic smem.
// ==========================================================================
template<int CIN, int ACT, int RES, int OUTF32>
__global__ __launch_bounds__(256, 1)
void gemm_tc(const __nv_bfloat16* __restrict__ in,
             const __nv_bfloat16* __restrict__ wgt,
             const float* __restrict__ bias,
             const float* __restrict__ res,
             void* __restrict__ outp)
{
    extern __shared__ __nv_bfloat16 smem[];
    __nv_bfloat16* As = smem;                    // NSTAGE * ASZ
    __nv_bfloat16* Bs = smem + NSTAGE * ASZ;     // NSTAGE * BSZ

    const int tid = threadIdx.x;
    const int bn = blockIdx.x * BN;
    const int bm = blockIdx.y * BM;
    const int bz = blockIdx.z;
    const int COUT = gridDim.y << 7;

    const __nv_bfloat16* inb = in + (size_t)bz * CIN * HW;

    const uint32_t sA = (uint32_t)__cvta_generic_to_shared(As);
    const uint32_t sB = (uint32_t)__cvta_generic_to_shared(Bs);

    // load-chunk coords (16B chunks of 8 bf16)
    const int a_r = tid >> 2, a_c = (tid & 3) << 3;     // A: 2 chunks/thread
    const int b_k = tid >> 5, b_n = (tid & 31) << 3;    // B: 4 chunks/thread

    // fragment coords
    const int lane = tid & 31, wid = tid >> 5;
    const int wm = (wid >> 2) * 64;
    const int wn = (wid & 3) * 64;
    const int lr = lane & 15;
    const int lc = (lane >> 4) << 3;

    float acc[4][8][4];
    #pragma unroll
    for (int i = 0; i < 4; i++)
        #pragma unroll
        for (int j = 0; j < 8; j++)
            #pragma unroll
            for (int k = 0; k < 4; k++) acc[i][j][k] = 0.0f;

    constexpr int NK = CIN / BK;

    auto load_stage = [&](int s, int k0) {
        const uint32_t aOff = sA + s * (ASZ * 2);
        const uint32_t bOff = sB + s * (BSZ * 2);
        cpasync16(aOff + (a_r * AST + a_c) * 2,
                  wgt + (size_t)(bm + a_r) * CIN + k0 + a_c);
        cpasync16(aOff + ((a_r + 64) * AST + a_c) * 2,
                  wgt + (size_t)(bm + a_r + 64) * CIN + k0 + a_c);
        #pragma unroll
        for (int q = 0; q < 4; q++)
            cpasync16(bOff + ((b_k + q * 8) * BSTR + b_n) * 2,
                      inb + (size_t)(k0 + b_k + q * 8) * HW + bn + b_n);
        asm volatile("cp.async.commit_group;\n");
    };

    load_stage(0, 0);
    load_stage(1, BK);

    for (int it = 0; it < NK; ++it) {
        asm volatile("cp.async.wait_group 1;\n");
        __syncthreads();

        if (it + 2 < NK) load_stage((it + 2) % NSTAGE, (it + 2) * BK);

        const int s = it % NSTAGE;
        const uint32_t aBase = sA + s * (ASZ * 2);
        const uint32_t bBase = sB + s * (BSZ * 2);

        #pragma unroll
        for (int kk = 0; kk < 2; kk++) {
            uint32_t a[4][4], b[4][4];
            #pragma unroll
            for (int mi = 0; mi < 4; mi++)
                ldsm4(a[mi], aBase + (((wm + mi * 16 + lr) * AST) + kk * 16 + lc) * 2);
            #pragma unroll
            for (int nt = 0; nt < 4; nt++)
                ldsm4t(b[nt], bBase + (((kk * 16 + lr) * BSTR) + wn + nt * 16 + lc) * 2);
            #pragma unroll
            for (int mi = 0; mi < 4; mi++)
                #pragma unroll
                for (int ni = 0; ni < 8; ni++)
                    mma16816(acc[mi][ni], a[mi], &b[ni >> 1][(ni & 1) * 2]);
        }
        __syncthreads();
    }

    // epilogue
    #pragma unroll
    for (int mi = 0; mi < 4; mi++) {
        const int m_base = bm + wm + mi * 16 + (lane >> 2);
        #pragma unroll
        for (int rg = 0; rg < 2; rg++) {
            const int mm = m_base + rg * 8;
            const float bv = bias[mm];
            #pragma unroll
            for (int ni = 0; ni < 8; ni++) {
                float v0 = acc[mi][ni][rg * 2 + 0] + bv;
                float v1 = acc[mi][ni][rg * 2 + 1] + bv;
                if (ACT == 1) { v0 = gelu_exact(v0); v1 = gelu_exact(v1); }
                const int n = bn + wn + ni * 8 + (lane & 3) * 2;
                const size_t off = ((size_t)bz * COUT + mm) * HW + n;
                if (RES) {
                    const float2 r = *(const float2*)(res + off);
                    v0 += r.x; v1 += r.y;
                }
                if (OUTF32) {
                    float2 o; o.x = v0; o.y = v1;
                    *(float2*)((float*)outp + off) = o;
                } else {
                    __nv_bfloat162 o;
                    o.x = __float2bfloat16(v0); o.y = __float2bfloat16(v1);
                    *(__nv_bfloat162*)((__nv_bfloat16*)outp + off) = o;
                }
            }
        }
    }
}

// ==========================================================================
// Kernel 3: depthwise 3x3 + bias + exact GELU. One (b,c) plane per block,
// haloed 82x82 smem, sliding-window registers (3 LDS/output), no div/mod.
// ==========================================================================
__global__ __launch_bounds__(320)
void dwgelu_kernel(const __nv_bfloat16* __restrict__ in,
                   const float* __restrict__ w,
                   const float* __restrict__ b,
                   __nv_bfloat16* __restrict__ out)
{
    __shared__ float pl[82 * 82];
    const int tid = threadIdx.x;
    const int bc = blockIdx.x;
    const int c = bc & (CC - 1);

    // zero halo (zero everything: cheap)
    for (int i = tid; i < 82 * 82; i += 320) pl[i] = 0.0f;
    __syncthreads();

    // load plane (bf16x2 vectorized)
    const __nv_bfloat162* src = (const __nv_bfloat162*)(in + (size_t)bc * HW);
    for (int i = tid; i < HW / 2; i += 320) {
        const int h = i / 40;
        const int w2 = i - h * 40;
        const float2 f = __bfloat1622float2(src[i]);
        const int base = (h + 1) * 82 + 2 * w2 + 1;
        pl[base] = f.x;
        pl[base + 1] = f.y;
    }
    __syncthreads();

    const float k0 = w[c*9+0], k1 = w[c*9+1], k2 = w[c*9+2];
    const float k3 = w[c*9+3], k4 = w[c*9+4], k5 = w[c*9+5];
    const float k6 = w[c*9+6], k7 = w[c*9+7], k8 = w[c*9+8];
    const float bv = b[c];

    const int wp = tid % 80;
    const int hq = tid / 80;
    const int h0 = hq * 20;

    // smem coords: plane (h,w) -> pl[(h+1)*82 + (w+1)]
    const float* p0 = &pl[h0 * 82 + wp];          // row h0-1, col wp-1
    float a0 = p0[0],  a1 = p0[1],  a2 = p0[2];
    float b0 = p0[82], b1 = p0[83], b2 = p0[84];

    __nv_bfloat16* dst = out + (size_t)bc * HW + h0 * 80 + wp;

    #pragma unroll 5
    for (int j = 0; j < 20; j++) {
        const float* pr = p0 + (j + 2) * 82;
        const float c0 = pr[0], c1 = pr[1], c2 = pr[2];
        float s = bv;
        s = fmaf(k0, a0, s); s = fmaf(k1, a1, s); s = fmaf(k2, a2, s);
        s = fmaf(k3, b0, s); s = fmaf(k4, b1, s); s = fmaf(k5, b2, s);
        s = fmaf(k6, c0, s); s = fmaf(k7, c1, s); s = fmaf(k8, c2, s);
        dst[j * 80] = __float2bfloat16(gelu_exact(s));
        a0 = b0; a1 = b1; a2 = b2;
        b0 = c0; b1 = c1; b2 = c2;
    }
}

// ==========================================================================
// launch
// ==========================================================================
extern "C" void kernel_launch(void* const* d_in, const int* in_sizes, int n_in,
                              void* d_out, int out_size)
{
    const float* x        = (const float*)d_in[0];
    const float* bn_gamma = (const float*)d_in[1];
    const float* bn_beta  = (const float*)d_in[2];
    const float* bn_mean  = (const float*)d_in[3];
    const float* bn_var   = (const float*)d_in[4];
    const float* a_real   = (const float*)d_in[5];
    const float* a_imag   = (const float*)d_in[6];
    const float* pi_w     = (const float*)d_in[7];
    const float* pi_b     = (const float*)d_in[8];
    const float* dw_w     = (const float*)d_in[9];
    const float* dw_b     = (const float*)d_in[10];
    const float* fpw_w    = (const float*)d_in[11];
    const float* fpw_b    = (const float*)d_in[12];
    const float* ffn1_w   = (const float*)d_in[13];
    const float* ffn1_b   = (const float*)d_in[14];
    const float* ffn2_w   = (const float*)d_in[15];
    const float* ffn2_b   = (const float*)d_in[16];
    const float* po_w     = (const float*)d_in[17];
    const float* po_b     = (const float*)d_in[18];
    const float* post_w   = (const float*)d_in[19];
    const float* post_b   = (const float*)d_in[20];
    float* out = (float*)d_out;

    float *h2f = nullptr, *biasc = nullptr;
    __nv_bfloat16 *h2b = nullptr, *b1 = nullptr, *b2 = nullptr, *wbf = nullptr;
    cudaGetSymbolAddress((void**)&h2f,   g_h2f);
    cudaGetSymbolAddress((void**)&h2b,   g_h2b);
    cudaGetSymbolAddress((void**)&b1,    g_b1);
    cudaGetSymbolAddress((void**)&b2,    g_b2);
    cudaGetSymbolAddress((void**)&wbf,   g_wbf);
    cudaGetSymbolAddress((void**)&biasc, g_biasc);

    // allow >48KB dynamic smem on the GEMM instantiations
    cudaFuncSetAttribute(gemm_tc<256, 0, 0, 0>, cudaFuncAttributeMaxDynamicSharedMemorySize, GSMEM);
    cudaFuncSetAttribute(gemm_tc<256, 1, 0, 0>, cudaFuncAttributeMaxDynamicSharedMemorySize, GSMEM);
    cudaFuncSetAttribute(gemm_tc<512, 0, 1, 0>, cudaFuncAttributeMaxDynamicSharedMemorySize, GSMEM);
    cudaFuncSetAttribute(gemm_tc<256, 0, 1, 1>, cudaFuncAttributeMaxDynamicSharedMemorySize, GSMEM);

    // 0) weight prep
    wconv_kernel<<<327680 / 256, 256>>>(pi_w, fpw_w, ffn1_w, post_w, wbf);
    wprod_kernel<<<256, 512>>>(po_w, ffn2_w, wbf + W_COMB);
    biasc_kernel<<<1, 256>>>(po_w, po_b, ffn2_b, biasc);

    // 1) BN + spectral gating (closed form)
    spectral_kernel<<<(BB * CC * HH) / 4, 320>>>(
        x, bn_gamma, bn_beta, bn_mean, bn_var, a_real, a_imag, h2f, h2b);

    dim3 g256(HW / BN, CC / BM, BB);        // (25, 2, 8)
    dim3 g512(HW / BN, (2 * CC) / BM, BB);  // (25, 4, 8)

    // 2) proj_in
    gemm_tc<256, 0, 0, 0><<<g256, 256, GSMEM>>>(h2b, wbf + W_PI, pi_b, nullptr, b1);
    // 3) dw3x3 + gelu
    dwgelu_kernel<<<BB * CC, 320>>>(b1, dw_w, dw_b, b2);
    // 4) fpw
    gemm_tc<256, 0, 0, 0><<<g256, 256, GSMEM>>>(b2, wbf + W_FPW, fpw_b, nullptr, b1);
    // 5) ffn1 + gelu (256 -> 512)
    gemm_tc<256, 1, 0, 0><<<g512, 256, GSMEM>>>(b1, wbf + W_FFN1, ffn1_b, nullptr, b2);
    // 6) combined (po @ ffn2): 512 -> 256, + res2 (h2 fp32)
    gemm_tc<512, 0, 1, 0><<<g256, 256, GSMEM>>>(b2, wbf + W_COMB, biasc, h2f, b1);
    // 7) post conv + outer residual (x fp32), fp32 out
    gemm_tc<256, 0, 1, 1><<<g256, 256, GSMEM>>>(b1, wbf + W_POST, post_b, x, out);
}

// round 5
// speedup vs baseline: 4.3102x; 1.3592x over previous
#include <cuda_runtime.h>
#include <cuda_bf16.h>
#include <cmath>
#include <cstdint>

#define BB 8
#define CC 256
#define HH 80
#define WW 80
#define HW (HH*WW)           // 6400
#define PI_F 3.14159265358979323846f

// conv1x1 GEMM tiling
#define BM 128
#define BN 256
#define BK 32
#define AST 40
#define BSTR 264
#define ASZ (BM*AST)
#define BSZ (BK*BSTR)
#define NSTAGE 3
#define GSMEM (NSTAGE*(ASZ+BSZ)*2)   // 81408 bytes

// spectral GEMM smem layout (dynamic)
#define SXF  (128*80)                 // fp32 x tile
#define SXB  (128*88)                 // bf16 x tile (padded)
#define STB  (80*88)                  // bf16 T tile (padded)
#define SPECSMEM (SXF*4 + SXB*2 + STB*2)   // 77568 bytes

// weight segment offsets in bf16 scratch
#define W_PI    0
#define W_FPW   65536
#define W_FFN1  131072       // 512x256
#define W_COMB  262144       // 256x512 (po @ ffn2)
#define W_POST  393216
#define W_TOTAL 458752

// -------------------- scratch (static device globals) --------------------
__device__ float          g_h2f[(size_t)BB*CC*HW];
__device__ __nv_bfloat16  g_h2b[(size_t)BB*CC*HW];
__device__ __nv_bfloat16  g_b1[(size_t)BB*2*CC*HW];
__device__ __nv_bfloat16  g_b2[(size_t)BB*2*CC*HW];
__device__ __nv_bfloat16  g_wbf[W_TOTAL];
__device__ float          g_biasc[CC];
__device__ __nv_bfloat16  g_T[80*80];
__device__ float          g_Ac[CC], g_Bc[CC], g_Cc[CC];

__device__ __forceinline__ float gelu_exact(float v) {
    return 0.5f * v * (1.0f + erff(v * 0.70710678118654752f));
}

// -------------------- PTX helpers ----------------------------------------
__device__ __forceinline__ void ldsm4(uint32_t* r, uint32_t addr) {
    asm volatile("ldmatrix.sync.aligned.m8n8.x4.shared.b16 {%0,%1,%2,%3}, [%4];\n"
        : "=r"(r[0]), "=r"(r[1]), "=r"(r[2]), "=r"(r[3]) : "r"(addr));
}
__device__ __forceinline__ void ldsm4t(uint32_t* r, uint32_t addr) {
    asm volatile("ldmatrix.sync.aligned.m8n8.x4.trans.shared.b16 {%0,%1,%2,%3}, [%4];\n"
        : "=r"(r[0]), "=r"(r[1]), "=r"(r[2]), "=r"(r[3]) : "r"(addr));
}
__device__ __forceinline__ void mma16816(float* d, const uint32_t* a, const uint32_t* b) {
    asm volatile(
        "mma.sync.aligned.m16n8k16.row.col.f32.bf16.bf16.f32 "
        "{%0,%1,%2,%3}, {%4,%5,%6,%7}, {%8,%9}, {%0,%1,%2,%3};\n"
        : "+f"(d[0]), "+f"(d[1]), "+f"(d[2]), "+f"(d[3])
        : "r"(a[0]), "r"(a[1]), "r"(a[2]), "r"(a[3]), "r"(b[0]), "r"(b[1]));
}
__device__ __forceinline__ void cpasync16(uint32_t smem, const void* g) {
    asm volatile("cp.async.cg.shared.global [%0], [%1], 16;\n" :: "r"(smem), "l"(g));
}

// ==========================================================================
// Prep: Hilbert circulant T[k][n] = t[(n-k) mod 80], bf16
// ==========================================================================
__global__ void tbuild_kernel(__nv_bfloat16* __restrict__ T)
{
    const int idx = blockIdx.x * 256 + threadIdx.x;
    if (idx >= 80 * 80) return;
    const int k = idx / 80, n = idx % 80;
    const int d = (n - k + 80) % 80;
    float t = 0.0f;
    if (d & 1) {
        float ang = PI_F * (float)d / 80.0f;
        t = -(2.0f / 80.0f) * (cosf(ang) / sinf(ang));
    }
    T[idx] = __float2bfloat16(t);
}

// Prep: per-channel BN+gate coefficients
__global__ void coef_kernel(const float* __restrict__ gamma, const float* __restrict__ beta,
                            const float* __restrict__ mean, const float* __restrict__ var,
                            const float* __restrict__ ar, const float* __restrict__ ai,
                            float* __restrict__ Ac, float* __restrict__ Bc, float* __restrict__ Cc)
{
    const int c = threadIdx.x;
    const float s  = gamma[c] * rsqrtf(var[c] + 1e-5f);
    const float tc = beta[c] - mean[c] * s;
    Ac[c] = ar[c] * s;
    Bc[c] = ai[c] * s;
    Cc[c] = ar[c] * tc;
}

// ==========================================================================
// Kernel 1: spectral gating as tensor-core GEMM.
//   u = x_rows @ T  (bf16 MMA),  h2 = Ac*x(fp32) + Bc*u + Cc
// 128 rows/block, K=N=80. 128 threads (4 warps, 32 rows each).
// ==========================================================================
__global__ __launch_bounds__(128, 1)
void spectral_mm(const float* __restrict__ x,
                 const __nv_bfloat16* __restrict__ T,
                 const float* __restrict__ Ac, const float* __restrict__ Bc,
                 const float* __restrict__ Cc,
                 float* __restrict__ h2f, __nv_bfloat16* __restrict__ h2b)
{
    extern __shared__ char sm[];
    float* xf = (float*)sm;                              // [128][80]
    __nv_bfloat16* xb = (__nv_bfloat16*)(sm + SXF * 4);  // [128][88]
    __nv_bfloat16* tb = (__nv_bfloat16*)(sm + SXF * 4 + SXB * 2); // [80][88]

    const int tid = threadIdx.x;
    const int rowbase = blockIdx.x * 128;
    const float* xg = x + (size_t)rowbase * 80;

    // load x tile: 2560 float4 chunks, 20/thread
    #pragma unroll
    for (int j = 0; j < 20; j++) {
        const int ci = tid + j * 128;         // float4 index
        const int r = ci / 20, c4 = (ci % 20) * 4;
        const float4 v = *(const float4*)(xg + r * 80 + c4);
        *(float4*)(xf + r * 80 + c4) = v;
        __nv_bfloat162* d = (__nv_bfloat162*)(xb + r * 88 + c4);
        d[0] = __floats2bfloat162_rn(v.x, v.y);
        d[1] = __floats2bfloat162_rn(v.z, v.w);
    }
    // load T: 3200 bf16x2, 25/thread
    const uint32_t* Tg = (const uint32_t*)T;
    #pragma unroll
    for (int j = 0; j < 25; j++) {
        const int ci = tid + j * 128;         // bf162 index
        const int r = ci / 40, c2 = (ci % 40) * 2;
        *(uint32_t*)(tb + r * 88 + c2) = Tg[ci];
    }
    __syncthreads();

    const int lane = tid & 31, w = tid >> 5;
    const int lr = lane & 15, lc = (lane >> 4) << 3;
    const uint32_t sXb = (uint32_t)__cvta_generic_to_shared(xb);
    const uint32_t sTb = (uint32_t)__cvta_generic_to_shared(tb);

    float acc[2][10][4];
    #pragma unroll
    for (int i = 0; i < 2; i++)
        #pragma unroll
        for (int j = 0; j < 10; j++)
            #pragma unroll
            for (int k = 0; k < 4; k++) acc[i][j][k] = 0.0f;

    #pragma unroll
    for (int k = 0; k < 5; k++) {
        uint32_t a[2][4], b[5][4];
        #pragma unroll
        for (int mt = 0; mt < 2; mt++)
            ldsm4(a[mt], sXb + ((w * 32 + mt * 16 + lr) * 88 + k * 16 + lc) * 2);
        #pragma unroll
        for (int nt = 0; nt < 5; nt++)
            ldsm4t(b[nt], sTb + ((k * 16 + lr) * 88 + nt * 16 + lc) * 2);
        #pragma unroll
        for (int mt = 0; mt < 2; mt++)
            #pragma unroll
            for (int n8 = 0; n8 < 10; n8++)
                mma16816(acc[mt][n8], a[mt], &b[n8 >> 1][(n8 & 1) * 2]);
    }

    // epilogue: h2 = Ac*x + Bc*u + Cc
    #pragma unroll
    for (int mt = 0; mt < 2; mt++) {
        #pragma unroll
        for (int rg = 0; rg < 2; rg++) {
            const int rl = w * 32 + mt * 16 + rg * 8 + (lane >> 2);
            const int grow = rowbase + rl;
            const int ch = (grow / HH) & (CC - 1);
            const float A = Ac[ch], Bv = Bc[ch], Cv = Cc[ch];
            float* of = h2f + (size_t)grow * 80;
            __nv_bfloat16* ob = h2b + (size_t)grow * 80;
            #pragma unroll
            for (int n8 = 0; n8 < 10; n8++) {
                const int col = n8 * 8 + (lane & 3) * 2;
                const float u0 = acc[mt][n8][rg * 2 + 0];
                const float u1 = acc[mt][n8][rg * 2 + 1];
                const float x0 = xf[rl * 80 + col];
                const float x1 = xf[rl * 80 + col + 1];
                float2 h;
                h.x = fmaf(A, x0, fmaf(Bv, u0, Cv));
                h.y = fmaf(A, x1, fmaf(Bv, u1, Cv));
                *(float2*)(of + col) = h;
                *(__nv_bfloat162*)(ob + col) = __floats2bfloat162_rn(h.x, h.y);
            }
        }
    }
}

// ==========================================================================
// Weight fp32 -> bf16 conversion (pi, fpw, ffn1, post)
// ==========================================================================
__global__ __launch_bounds__(256)
void wconv_kernel(const float* __restrict__ pi, const float* __restrict__ fpw,
                  const float* __restrict__ f1, const float* __restrict__ post,
                  __nv_bfloat16* __restrict__ o)
{
    const int i = blockIdx.x * 256 + threadIdx.x;
    float v; int dst;
    if      (i < 65536)  { v = pi[i];            dst = W_PI   + i; }
    else if (i < 131072) { v = fpw[i - 65536];   dst = W_FPW  + (i - 65536); }
    else if (i < 262144) { v = f1[i - 131072];   dst = W_FFN1 + (i - 131072); }
    else                 { v = post[i - 262144]; dst = W_POST + (i - 262144); }
    o[dst] = __float2bfloat16(v);
}

// W_comb = po_w @ ffn2_w (256x256 @ 256x512, fp32 accum -> bf16)
__global__ __launch_bounds__(512)
void wprod_kernel(const float* __restrict__ po_w, const float* __restrict__ ffn2_w,
                  __nv_bfloat16* __restrict__ o)
{
    __shared__ float prow[256];
    const int oo = blockIdx.x;
    for (int i = threadIdx.x; i < 256; i += 512) prow[i] = po_w[oo * 256 + i];
    __syncthreads();
    float s = 0.0f;
    #pragma unroll 8
    for (int c = 0; c < 256; c++)
        s = fmaf(prow[c], ffn2_w[(size_t)c * 512 + threadIdx.x], s);
    o[(size_t)oo * 512 + threadIdx.x] = __float2bfloat16(s);
}

// bias_comb = po_b + po_w @ ffn2_b
__global__ void biasc_kernel(const float* __restrict__ po_w, const float* __restrict__ po_b,
                             const float* __restrict__ ffn2_b, float* __restrict__ o)
{
    const int oo = threadIdx.x;
    float s = po_b[oo];
    for (int c = 0; c < 256; c++)
        s = fmaf(po_w[oo * 256 + c], ffn2_b[c], s);
    o[oo] = s;
}

// ==========================================================================
// Kernel 2: tensor-core conv1x1 GEMM (128x256x32, 3-stage cp.async)
// ==========================================================================
template<int CIN, int ACT, int RES, int OUTF32>
__global__ __launch_bounds__(256, 1)
void gemm_tc(const __nv_bfloat16* __restrict__ in,
             const __nv_bfloat16* __restrict__ wgt,
             const float* __restrict__ bias,
             const float* __restrict__ res,
             void* __restrict__ outp)
{
    extern __shared__ __nv_bfloat16 smem[];
    __nv_bfloat16* As = smem;
    __nv_bfloat16* Bs = smem + NSTAGE * ASZ;

    const int tid = threadIdx.x;
    const int bn = blockIdx.x * BN;
    const int bm = blockIdx.y * BM;
    const int bz = blockIdx.z;
    const int COUT = gridDim.y << 7;

    const __nv_bfloat16* inb = in + (size_t)bz * CIN * HW;

    const uint32_t sA = (uint32_t)__cvta_generic_to_shared(As);
    const uint32_t sB = (uint32_t)__cvta_generic_to_shared(Bs);

    const int a_r = tid >> 2, a_c = (tid & 3) << 3;
    const int b_k = tid >> 5, b_n = (tid & 31) << 3;

    const int lane = tid & 31, wid = tid >> 5;
    const int wm = (wid >> 2) * 64;
    const int wn = (wid & 3) * 64;
    const int lr = lane & 15;
    const int lc = (lane >> 4) << 3;

    float acc[4][8][4];
    #pragma unroll
    for (int i = 0; i < 4; i++)
        #pragma unroll
        for (int j = 0; j < 8; j++)
            #pragma unroll
            for (int k = 0; k < 4; k++) acc[i][j][k] = 0.0f;

    constexpr int NK = CIN / BK;

    auto load_stage = [&](int s, int k0) {
        const uint32_t aOff = sA + s * (ASZ * 2);
        const uint32_t bOff = sB + s * (BSZ * 2);
        cpasync16(aOff + (a_r * AST + a_c) * 2,
                  wgt + (size_t)(bm + a_r) * CIN + k0 + a_c);
        cpasync16(aOff + ((a_r + 64) * AST + a_c) * 2,
                  wgt + (size_t)(bm + a_r + 64) * CIN + k0 + a_c);
        #pragma unroll
        for (int q = 0; q < 4; q++)
            cpasync16(bOff + ((b_k + q * 8) * BSTR + b_n) * 2,
                      inb + (size_t)(k0 + b_k + q * 8) * HW + bn + b_n);
        asm volatile("cp.async.commit_group;\n");
    };

    load_stage(0, 0);
    load_stage(1, BK);

    for (int it = 0; it < NK; ++it) {
        asm volatile("cp.async.wait_group 1;\n");
        __syncthreads();

        if (it + 2 < NK) load_stage((it + 2) % NSTAGE, (it + 2) * BK);

        const int s = it % NSTAGE;
        const uint32_t aBase = sA + s * (ASZ * 2);
        const uint32_t bBase = sB + s * (BSZ * 2);

        #pragma unroll
        for (int kk = 0; kk < 2; kk++) {
            uint32_t a[4][4], b[4][4];
            #pragma unroll
            for (int mi = 0; mi < 4; mi++)
                ldsm4(a[mi], aBase + (((wm + mi * 16 + lr) * AST) + kk * 16 + lc) * 2);
            #pragma unroll
            for (int nt = 0; nt < 4; nt++)
                ldsm4t(b[nt], bBase + (((kk * 16 + lr) * BSTR) + wn + nt * 16 + lc) * 2);
            #pragma unroll
            for (int mi = 0; mi < 4; mi++)
                #pragma unroll
                for (int ni = 0; ni < 8; ni++)
                    mma16816(acc[mi][ni], a[mi], &b[ni >> 1][(ni & 1) * 2]);
        }
        __syncthreads();
    }

    #pragma unroll
    for (int mi = 0; mi < 4; mi++) {
        const int m_base = bm + wm + mi * 16 + (lane >> 2);
        #pragma unroll
        for (int rg = 0; rg < 2; rg++) {
            const int mm = m_base + rg * 8;
            const float bv = bias[mm];
            #pragma unroll
            for (int ni = 0; ni < 8; ni++) {
                float v0 = acc[mi][ni][rg * 2 + 0] + bv;
                float v1 = acc[mi][ni][rg * 2 + 1] + bv;
                if (ACT == 1) { v0 = gelu_exact(v0); v1 = gelu_exact(v1); }
                const int n = bn + wn + ni * 8 + (lane & 3) * 2;
                const size_t off = ((size_t)bz * COUT + mm) * HW + n;
                if (RES) {
                    const float2 r = *(const float2*)(res + off);
                    v0 += r.x; v1 += r.y;
                }
                if (OUTF32) {
                    float2 o; o.x = v0; o.y = v1;
                    *(float2*)((float*)outp + off) = o;
                } else {
                    __nv_bfloat162 o;
                    o.x = __float2bfloat16(v0); o.y = __float2bfloat16(v1);
                    *(__nv_bfloat162*)((__nv_bfloat16*)outp + off) = o;
                }
            }
        }
    }
}

// ==========================================================================
// Kernel 3: depthwise 3x3 + bias + exact GELU (haloed smem, sliding window)
// ==========================================================================
__global__ __launch_bounds__(320)
void dwgelu_kernel(const __nv_bfloat16* __restrict__ in,
                   const float* __restrict__ w,
                   const float* __restrict__ b,
                   __nv_bfloat16* __restrict__ out)
{
    __shared__ float pl[82 * 82];
    const int tid = threadIdx.x;
    const int bc = blockIdx.x;
    const int c = bc & (CC - 1);

    for (int i = tid; i < 82 * 82; i += 320) pl[i] = 0.0f;
    __syncthreads();

    const __nv_bfloat162* src = (const __nv_bfloat162*)(in + (size_t)bc * HW);
    for (int i = tid; i < HW / 2; i += 320) {
        const int h = i / 40;
        const int w2 = i - h * 40;
        const float2 f = __bfloat1622float2(src[i]);
        const int base = (h + 1) * 82 + 2 * w2 + 1;
        pl[base] = f.x;
        pl[base + 1] = f.y;
    }
    __syncthreads();

    const float k0 = w[c*9+0], k1 = w[c*9+1], k2 = w[c*9+2];
    const float k3 = w[c*9+3], k4 = w[c*9+4], k5 = w[c*9+5];
    const float k6 = w[c*9+6], k7 = w[c*9+7], k8 = w[c*9+8];
    const float bv = b[c];

    const int wp = tid % 80;
    const int hq = tid / 80;
    const int h0 = hq * 20;

    const float* p0 = &pl[h0 * 82 + wp];
    float a0 = p0[0],  a1 = p0[1],  a2 = p0[2];
    float b0 = p0[82], b1 = p0[83], b2 = p0[84];

    __nv_bfloat16* dst = out + (size_t)bc * HW + h0 * 80 + wp;

    #pragma unroll 5
    for (int j = 0; j < 20; j++) {
        const float* pr = p0 + (j + 2) * 82;
        const float c0 = pr[0], c1 = pr[1], c2 = pr[2];
        float s = bv;
        s = fmaf(k0, a0, s); s = fmaf(k1, a1, s); s = fmaf(k2, a2, s);
        s = fmaf(k3, b0, s); s = fmaf(k4, b1, s); s = fmaf(k5, b2, s);
        s = fmaf(k6, c0, s); s = fmaf(k7, c1, s); s = fmaf(k8, c2, s);
        dst[j * 80] = __float2bfloat16(gelu_exact(s));
        a0 = b0; a1 = b1; a2 = b2;
        b0 = c0; b1 = c1; b2 = c2;
    }
}

// ==========================================================================
// launch
// ==========================================================================
extern "C" void kernel_launch(void* const* d_in, const int* in_sizes, int n_in,
                              void* d_out, int out_size)
{
    const float* x        = (const float*)d_in[0];
    const float* bn_gamma = (const float*)d_in[1];
    const float* bn_beta  = (const float*)d_in[2];
    const float* bn_mean  = (const float*)d_in[3];
    const float* bn_var   = (const float*)d_in[4];
    const float* a_real   = (const float*)d_in[5];
    const float* a_imag   = (const float*)d_in[6];
    const float* pi_w     = (const float*)d_in[7];
    const float* pi_b     = (const float*)d_in[8];
    const float* dw_w     = (const float*)d_in[9];
    const float* dw_b     = (const float*)d_in[10];
    const float* fpw_w    = (const float*)d_in[11];
    const float* fpw_b    = (const float*)d_in[12];
    const float* ffn1_w   = (const float*)d_in[13];
    const float* ffn1_b   = (const float*)d_in[14];
    const float* ffn2_w   = (const float*)d_in[15];
    const float* ffn2_b   = (const float*)d_in[16];
    const float* po_w     = (const float*)d_in[17];
    const float* po_b     = (const float*)d_in[18];
    const float* post_w   = (const float*)d_in[19];
    const float* post_b   = (const float*)d_in[20];
    float* out = (float*)d_out;

    float *h2f = nullptr, *biasc = nullptr, *Ac = nullptr, *Bc = nullptr, *Cc = nullptr;
    __nv_bfloat16 *h2b = nullptr, *b1 = nullptr, *b2 = nullptr, *wbf = nullptr, *T = nullptr;
    cudaGetSymbolAddress((void**)&h2f,   g_h2f);
    cudaGetSymbolAddress((void**)&h2b,   g_h2b);
    cudaGetSymbolAddress((void**)&b1,    g_b1);
    cudaGetSymbolAddress((void**)&b2,    g_b2);
    cudaGetSymbolAddress((void**)&wbf,   g_wbf);
    cudaGetSymbolAddress((void**)&biasc, g_biasc);
    cudaGetSymbolAddress((void**)&T,     g_T);
    cudaGetSymbolAddress((void**)&Ac,    g_Ac);
    cudaGetSymbolAddress((void**)&Bc,    g_Bc);
    cudaGetSymbolAddress((void**)&Cc,    g_Cc);

    cudaFuncSetAttribute(gemm_tc<256, 0, 0, 0>, cudaFuncAttributeMaxDynamicSharedMemorySize, GSMEM);
    cudaFuncSetAttribute(gemm_tc<256, 1, 0, 0>, cudaFuncAttributeMaxDynamicSharedMemorySize, GSMEM);
    cudaFuncSetAttribute(gemm_tc<512, 0, 1, 0>, cudaFuncAttributeMaxDynamicSharedMemorySize, GSMEM);
    cudaFuncSetAttribute(gemm_tc<256, 0, 1, 1>, cudaFuncAttributeMaxDynamicSharedMemorySize, GSMEM);
    cudaFuncSetAttribute(spectral_mm, cudaFuncAttributeMaxDynamicSharedMemorySize, SPECSMEM);

    // 0) prep
    tbuild_kernel<<<25, 256>>>(T);
    coef_kernel<<<1, 256>>>(bn_gamma, bn_beta, bn_mean, bn_var, a_real, a_imag, Ac, Bc, Cc);
    wconv_kernel<<<327680 / 256, 256>>>(pi_w, fpw_w, ffn1_w, post_w, wbf);
    wprod_kernel<<<256, 512>>>(po_w, ffn2_w, wbf + W_COMB);
    biasc_kernel<<<1, 256>>>(po_w, po_b, ffn2_b, biasc);

    // 1) BN + spectral gating as tensor-core GEMM
    spectral_mm<<<(BB * CC * HH) / 128, 128, SPECSMEM>>>(x, T, Ac, Bc, Cc, h2f, h2b);

    dim3 g256(HW / BN, CC / BM, BB);        // (25, 2, 8)
    dim3 g512(HW / BN, (2 * CC) / BM, BB);  // (25, 4, 8)

    // 2) proj_in
    gemm_tc<256, 0, 0, 0><<<g256, 256, GSMEM>>>(h2b, wbf + W_PI, pi_b, nullptr, b1);
    // 3) dw3x3 + gelu
    dwgelu_kernel<<<BB * CC, 320>>>(b1, dw_w, dw_b, b2);
    // 4) fpw
    gemm_tc<256, 0, 0, 0><<<g256, 256, GSMEM>>>(b2, wbf + W_FPW, fpw_b, nullptr, b1);
    // 5) ffn1 + gelu (256 -> 512)
    gemm_tc<256, 1, 0, 0><<<g512, 256, GSMEM>>>(b1, wbf + W_FFN1, ffn1_b, nullptr, b2);
    // 6) combined (po @ ffn2): 512 -> 256, + res2 (h2 fp32)
    gemm_tc<512, 0, 1, 0><<<g256, 256, GSMEM>>>(b2, wbf + W_COMB, biasc, h2f, b1);
    // 7) post conv + outer residual (x fp32), fp32 out
    gemm_tc<256, 0, 1, 1><<<g256, 256, GSMEM>>>(b1, wbf + W_POST, post_b, x, out);
}